// round 9
// baseline (speedup 1.0000x reference)
#include <cuda_runtime.h>
#include <cstdint>
#include <cmath>

// Problem constants (fixed by the dataset)
#define T_TOK 1024
#define H_DIM 2048
#define I_DIM 768
#define E_NUM 8
#define K_TOP 2
#define NROWS (T_TOK * K_TOP)      // 2048 permuted rows

#define BM 128
#define MAX_TILES 24

// ---------------- scratch (no allocations allowed) ----------------
__device__ int   g_row_src[NROWS];
__device__ int   g_pos[NROWS];
__device__ int   g_tile_expert[MAX_TILES];
__device__ int   g_tile_row[MAX_TILES];
__device__ int   g_tile_end[MAX_TILES];
__device__ int   g_num_tiles;
__device__ float g_xc[T_TOK * H_DIM];     // tf32-rounded hidden_states
__device__ float g_act[NROWS * I_DIM];    // tf32-rounded swiglu output
__device__ float g_fc2[NROWS * H_DIM];

// ---------------- PTX helpers (all sm_80-level, no 'a' features) ----------------
__device__ __forceinline__ uint32_t s2u(const void* p) {
    uint32_t a;
    asm("{ .reg .u64 t; cvta.to.shared.u64 t, %1; cvt.u32.u64 %0, t; }" : "=r"(a) : "l"(p));
    return a;
}
__device__ __forceinline__ void cp16(uint32_t dst, const void* src, uint32_t sz) {
    asm volatile("cp.async.cg.shared.global [%0], [%1], 16, %2;" :: "r"(dst), "l"(src), "r"(sz));
}
__device__ __forceinline__ void cp_commit() { asm volatile("cp.async.commit_group;" ::: "memory"); }
template<int N> __device__ __forceinline__ void cp_wait() {
    asm volatile("cp.async.wait_group %0;" :: "n"(N) : "memory");
}
__device__ __forceinline__ void ldsm4(uint32_t r[4], uint32_t addr) {
    asm volatile("ldmatrix.sync.aligned.m8n8.x4.shared.b16 {%0,%1,%2,%3}, [%4];"
        : "=r"(r[0]), "=r"(r[1]), "=r"(r[2]), "=r"(r[3]) : "r"(addr));
}
__device__ __forceinline__ uint32_t f2tf_f(float x) {
    uint32_t r;
    asm("cvt.rna.tf32.f32 %0, %1;" : "=r"(r) : "f"(x));
    return r;
}
__device__ __forceinline__ float tfr(float x) {           // tf32 round, keep as float bits
    return __uint_as_float(f2tf_f(x));
}
__device__ __forceinline__ void mma8(float* c, const uint32_t* a, uint32_t b0, uint32_t b1) {
    asm volatile(
        "mma.sync.aligned.m16n8k8.row.col.f32.tf32.tf32.f32 "
        "{%0,%1,%2,%3}, {%4,%5,%6,%7}, {%8,%9}, {%0,%1,%2,%3};"
        : "+f"(c[0]), "+f"(c[1]), "+f"(c[2]), "+f"(c[3])
        : "r"(a[0]), "r"(a[1]), "r"(a[2]), "r"(a[3]), "r"(b0), "r"(b1));
}

// SMEM layout: [0,512) s_tok ; [1024 ...) THREE stages of {A 16KB, B 17408B (32 x 136 f)}
#define BPAD 136
#define STAGE_BYTES 33792
#define OFF_A(b) (1024 + (b) * STAGE_BYTES)
#define OFF_B(b) (OFF_A(b) + 16384)
#define SMEM_TOTAL 102400           // 1024 + 3*33792; gemm1 epilogue Es reuses it

// ---------------- setup ----------------
__global__ void setup_kernel(const int* __restrict__ sel) {
    __shared__ int cnt[E_NUM];
    __shared__ int run[E_NUM];
    int tid = threadIdx.x;
    if (tid < E_NUM) cnt[tid] = 0;
    __syncthreads();
    for (int i = tid; i < NROWS; i += blockDim.x)
        atomicAdd(&cnt[sel[i]], 1);
    __syncthreads();
    if (tid == 0) {
        int s = 0, nt = 0;
        for (int e = 0; e < E_NUM; e++) {
            run[e] = s;
            int c = cnt[e];
            for (int r = 0; r < c; r += BM) {
                g_tile_expert[nt] = e;
                g_tile_row[nt]    = s + r;
                g_tile_end[nt]    = s + c;
                nt++;
            }
            s += c;
        }
        g_num_tiles = nt;
    }
    __syncthreads();
    for (int i = tid; i < NROWS; i += blockDim.x) {
        int e = sel[i];
        int p = atomicAdd(&run[e], 1);
        g_row_src[p] = i;
        g_pos[i] = p;
    }
}

// ---------------- cvtx: g_xc = tf32(x) ----------------
__global__ void __launch_bounds__(256)
cvtx_kernel(const float* __restrict__ x) {
    int i = blockIdx.x * blockDim.x + threadIdx.x;
    if (i >= T_TOK * (H_DIM / 4)) return;
    float4 v = reinterpret_cast<const float4*>(x)[i];
    v.x = tfr(v.x); v.y = tfr(v.y); v.z = tfr(v.z); v.w = tfr(v.w);
    reinterpret_cast<float4*>(g_xc)[i] = v;
}

// ---------------- GEMM1: act = swiglu( Xc_gather @ W1[e] ), tf32 mma.sync ----------------
// Block: 128 rows x (gate 64 + up 64). Warps 2x4, warp tile 64x32. Pipelined frags.
__global__ void __launch_bounds__(256, 2)
gemm1_kernel(const float* __restrict__ w1) {
    extern __shared__ char smem[];
    uint32_t sb = s2u(smem);
    int mt = blockIdx.x;
    if (mt >= g_num_tiles) return;
    int e = g_tile_expert[mt], row0 = g_tile_row[mt], rend = g_tile_end[mt];
    int col0g = blockIdx.y * 64;

    int tid = threadIdx.x, lane = tid & 31, wid = tid >> 5;
    int warpM = wid >> 2, warpN = wid & 3;
    int gid = lane >> 2, tig = lane & 3;

    int* s_tok = (int*)smem;
    if (tid < 128) {
        int r = row0 + tid;
        s_tok[tid] = (r < rend) ? (g_row_src[r] / K_TOP) : -1;
    }
    __syncthreads();

    const float* W = w1 + (size_t)e * H_DIM * (2 * I_DIM);
    int am = tid >> 1;
    int tokm = s_tok[am];
    const float* asrc = g_xc + (size_t)(tokm < 0 ? 0 : tokm) * H_DIM;
    uint32_t asz = (tokm < 0) ? 0u : 16u;
    int ac0 = (tid & 1) * 4;
    int akey = am & 7;

    auto load_chunk = [&](int ci, int buf) {
        int k0 = ci * 32;
        uint32_t Ab = sb + OFF_A(buf);
        #pragma unroll
        for (int c = 0; c < 4; c++) {
            int cc = ac0 + c;
            cp16(Ab + am * 128 + ((cc ^ akey) << 4), asrc + k0 + cc * 4, asz);
        }
        uint32_t Bb = sb + OFF_B(buf);
        #pragma unroll
        for (int it = 0; it < 4; it++) {
            int q = tid + it * 256;
            int k = q >> 5, c16 = q & 31, n = c16 * 4;
            const float* src = (n < 64)
                ? W + (size_t)(k0 + k) * (2 * I_DIM) + col0g + n
                : W + (size_t)(k0 + k) * (2 * I_DIM) + I_DIM + col0g + (n - 64);
            cp16(Bb + k * (BPAD * 4) + n * 4, src, 16);
        }
        cp_commit();
    };

    int mlane = lane & 15, extra = lane >> 4, key = lane & 7;
    int boff = tig * BPAD + warpN * 32 + gid;
    uint32_t arow = (uint32_t)((warpM * 64 + mlane) * 128);

    float acc[4][4][4] = {};
    uint32_t af[2][4][4];
    uint32_t bf[2][8];
    const int NC = H_DIM / 32;   // 64
    load_chunk(0, 0);
    load_chunk(1, 1);
    int bc = 0;
    for (int i = 0; i < NC; i++) {
        cp_wait<1>();
        __syncthreads();
        int bn = bc + 2; if (bn >= 3) bn -= 3;
        if (i + 2 < NC) load_chunk(i + 2, bn);
        else            cp_commit();

        uint32_t Ab = sb + OFF_A(bc) + arow;
        const float* Bsp = (const float*)(smem + OFF_B(bc));
        // preload ks=0 fragments
        #pragma unroll
        for (int mi = 0; mi < 4; mi++)
            ldsm4(af[0][mi], Ab + mi * (16 * 128) + ((extra ^ key) << 4));
        #pragma unroll
        for (int j = 0; j < 4; j++) {
            bf[0][2 * j]     = f2tf_f(Bsp[boff + j * 8]);
            bf[0][2 * j + 1] = f2tf_f(Bsp[boff + j * 8 + 4 * BPAD]);
        }
        #pragma unroll
        for (int ks = 0; ks < 4; ks++) {
            int cur = ks & 1, nxt = cur ^ 1;
            if (ks < 3) {   // prefetch ks+1 fragments BEFORE the mma block
                #pragma unroll
                for (int mi = 0; mi < 4; mi++)
                    ldsm4(af[nxt][mi], Ab + mi * (16 * 128)
                          + (((((ks + 1) << 1) | extra) ^ key) << 4));
                #pragma unroll
                for (int j = 0; j < 4; j++) {
                    bf[nxt][2 * j]     = f2tf_f(Bsp[boff + (ks + 1) * (8 * BPAD) + j * 8]);
                    bf[nxt][2 * j + 1] = f2tf_f(Bsp[boff + (ks + 1) * (8 * BPAD) + j * 8 + 4 * BPAD]);
                }
            }
            #pragma unroll
            for (int j = 0; j < 4; j++)
                #pragma unroll
                for (int mi = 0; mi < 4; mi++)
                    mma8(acc[mi][j], af[cur][mi], bf[cur][2 * j], bf[cur][2 * j + 1]);
        }
        bc = (bc + 1 == 3) ? 0 : bc + 1;
    }

    // epilogue: frags -> smem, then swiglu (tf32-rounded) -> g_act
    __syncthreads();             // Es overlaps the pipeline buffers
    float* Es = (float*)(smem + 1024);
    #pragma unroll
    for (int mi = 0; mi < 4; mi++)
        #pragma unroll
        for (int j = 0; j < 4; j++) {
            int row = warpM * 64 + mi * 16 + gid;
            int col = warpN * 32 + j * 8 + 2 * tig;
            *(float2*)&Es[row * 132 + col]       = make_float2(acc[mi][j][0], acc[mi][j][1]);
            *(float2*)&Es[(row + 8) * 132 + col] = make_float2(acc[mi][j][2], acc[mi][j][3]);
        }
    __syncthreads();

    int rr = tid >> 1;
    int r  = row0 + rr;
    int cb = (tid & 1) * 32;
    if (r < rend) {
        float* dst = g_act + (size_t)r * I_DIM + col0g + cb;
        #pragma unroll
        for (int jj = 0; jj < 32; jj += 4) {
            float4 gv = *(float4*)&Es[rr * 132 + cb + jj];
            float4 uv = *(float4*)&Es[rr * 132 + 64 + cb + jj];
            float4 o;
            o.x = tfr(gv.x * (1.0f / (1.0f + __expf(-gv.x))) * uv.x);
            o.y = tfr(gv.y * (1.0f / (1.0f + __expf(-gv.y))) * uv.y);
            o.z = tfr(gv.z * (1.0f / (1.0f + __expf(-gv.z))) * uv.z);
            o.w = tfr(gv.w * (1.0f / (1.0f + __expf(-gv.w))) * uv.w);
            *(float4*)(dst + jj) = o;
        }
    }
}

// ---------------- GEMM2: fc2 = act @ W2[e], tf32 mma.sync ----------------
// Block: 128 rows x 128 cols. Warps 2x4, warp tile 64x32. Pipelined frags.
__global__ void __launch_bounds__(256, 2)
gemm2_kernel(const float* __restrict__ w2) {
    extern __shared__ char smem[];
    uint32_t sb = s2u(smem);
    int mt = blockIdx.x;
    if (mt >= g_num_tiles) return;
    int e = g_tile_expert[mt], row0 = g_tile_row[mt], rend = g_tile_end[mt];
    int col0 = blockIdx.y * 128;

    int tid = threadIdx.x, lane = tid & 31, wid = tid >> 5;
    int warpM = wid >> 2, warpN = wid & 3;
    int gid = lane >> 2, tig = lane & 3;

    const float* W = w2 + (size_t)e * I_DIM * H_DIM;
    int am = tid >> 1;
    int rrow = row0 + am; if (rrow >= NROWS) rrow = NROWS - 1;   // clamp; masked later
    const float* asrc = g_act + (size_t)rrow * I_DIM;
    int ac0 = (tid & 1) * 4;
    int akey = am & 7;

    auto load_chunk = [&](int ci, int buf) {
        int k0 = ci * 32;
        uint32_t Ab = sb + OFF_A(buf);
        #pragma unroll
        for (int c = 0; c < 4; c++) {
            int cc = ac0 + c;
            cp16(Ab + am * 128 + ((cc ^ akey) << 4), asrc + k0 + cc * 4, 16);
        }
        uint32_t Bb = sb + OFF_B(buf);
        #pragma unroll
        for (int it = 0; it < 4; it++) {
            int q = tid + it * 256;
            int k = q >> 5, c16 = q & 31, n = c16 * 4;
            cp16(Bb + k * (BPAD * 4) + n * 4, W + (size_t)(k0 + k) * H_DIM + col0 + n, 16);
        }
        cp_commit();
    };

    int mlane = lane & 15, extra = lane >> 4, key = lane & 7;
    int boff = tig * BPAD + warpN * 32 + gid;
    uint32_t arow = (uint32_t)((warpM * 64 + mlane) * 128);

    float acc[4][4][4] = {};
    uint32_t af[2][4][4];
    uint32_t bf[2][8];
    const int NC = I_DIM / 32;   // 24
    load_chunk(0, 0);
    load_chunk(1, 1);
    int bc = 0;
    for (int i = 0; i < NC; i++) {
        cp_wait<1>();
        __syncthreads();
        int bn = bc + 2; if (bn >= 3) bn -= 3;
        if (i + 2 < NC) load_chunk(i + 2, bn);
        else            cp_commit();

        uint32_t Ab = sb + OFF_A(bc) + arow;
        const float* Bsp = (const float*)(smem + OFF_B(bc));
        #pragma unroll
        for (int mi = 0; mi < 4; mi++)
            ldsm4(af[0][mi], Ab + mi * (16 * 128) + ((extra ^ key) << 4));
        #pragma unroll
        for (int j = 0; j < 4; j++) {
            bf[0][2 * j]     = f2tf_f(Bsp[boff + j * 8]);
            bf[0][2 * j + 1] = f2tf_f(Bsp[boff + j * 8 + 4 * BPAD]);
        }
        #pragma unroll
        for (int ks = 0; ks < 4; ks++) {
            int cur = ks & 1, nxt = cur ^ 1;
            if (ks < 3) {
                #pragma unroll
                for (int mi = 0; mi < 4; mi++)
                    ldsm4(af[nxt][mi], Ab + mi * (16 * 128)
                          + (((((ks + 1) << 1) | extra) ^ key) << 4));
                #pragma unroll
                for (int j = 0; j < 4; j++) {
                    bf[nxt][2 * j]     = f2tf_f(Bsp[boff + (ks + 1) * (8 * BPAD) + j * 8]);
                    bf[nxt][2 * j + 1] = f2tf_f(Bsp[boff + (ks + 1) * (8 * BPAD) + j * 8 + 4 * BPAD]);
                }
            }
            #pragma unroll
            for (int j = 0; j < 4; j++)
                #pragma unroll
                for (int mi = 0; mi < 4; mi++)
                    mma8(acc[mi][j], af[cur][mi], bf[cur][2 * j], bf[cur][2 * j + 1]);
        }
        bc = (bc + 1 == 3) ? 0 : bc + 1;
    }

    // epilogue: direct to g_fc2
    #pragma unroll
    for (int mi = 0; mi < 4; mi++) {
        int row = row0 + warpM * 64 + mi * 16 + gid;
        #pragma unroll
        for (int j = 0; j < 4; j++) {
            int col = col0 + warpN * 32 + j * 8 + 2 * tig;
            if (row < rend)
                *(float2*)&g_fc2[(size_t)row * H_DIM + col] =
                    make_float2(acc[mi][j][0], acc[mi][j][1]);
            if (row + 8 < rend)
                *(float2*)&g_fc2[(size_t)(row + 8) * H_DIM + col] =
                    make_float2(acc[mi][j][2], acc[mi][j][3]);
        }
    }
}

// ---------------- combine ----------------
__global__ void __launch_bounds__(256)
combine_kernel(const float* __restrict__ rw, float* __restrict__ out) {
    int i = blockIdx.x * blockDim.x + threadIdx.x;
    if (i >= T_TOK * (H_DIM / 4)) return;
    int t  = i >> 9;
    int h4 = i & 511;
    int p0 = g_pos[2 * t];
    int p1 = g_pos[2 * t + 1];
    float w0 = rw[2 * t];
    float w1 = rw[2 * t + 1];
    float4 v0 = *reinterpret_cast<const float4*>(&g_fc2[(size_t)p0 * H_DIM + h4 * 4]);
    float4 v1 = *reinterpret_cast<const float4*>(&g_fc2[(size_t)p1 * H_DIM + h4 * 4]);
    float4 o;
    o.x = w0 * v0.x + w1 * v1.x;
    o.y = w0 * v0.y + w1 * v1.y;
    o.z = w0 * v0.z + w1 * v1.z;
    o.w = w0 * v0.w + w1 * v1.w;
    reinterpret_cast<float4*>(out)[i] = o;
}

// ---------------- launch ----------------
extern "C" void kernel_launch(void* const* d_in, const int* in_sizes, int n_in,
                              void* d_out, int out_size) {
    const float* x   = (const float*)d_in[0];   // hidden_states [T, H]
    const float* rw  = (const float*)d_in[1];   // routing_weights [T, K]
    const float* w1  = (const float*)d_in[2];   // gate_up_proj [E, H, 2I]
    const float* w2  = (const float*)d_in[3];   // down_proj   [E, I, H]
    const int*   sel = (const int*)d_in[4];     // selected_experts [T, K]
    float* out = (float*)d_out;                 // [T, H] fp32

    cudaFuncSetAttribute(gemm1_kernel, cudaFuncAttributeMaxDynamicSharedMemorySize, SMEM_TOTAL);
    cudaFuncSetAttribute(gemm2_kernel, cudaFuncAttributeMaxDynamicSharedMemorySize, SMEM_TOTAL);

    setup_kernel<<<1, 256>>>(sel);
    cvtx_kernel<<<(T_TOK * H_DIM / 4 + 255) / 256, 256>>>(x);
    gemm1_kernel<<<dim3(MAX_TILES, I_DIM / 64), 256, SMEM_TOTAL>>>(w1);
    gemm2_kernel<<<dim3(MAX_TILES, H_DIM / 128), 256, SMEM_TOTAL>>>(w2);
    combine_kernel<<<(T_TOK * H_DIM / 4 + 255) / 256, 256>>>(rw, out);
}

// round 10
// speedup vs baseline: 1.1763x; 1.1763x over previous
#include <cuda_runtime.h>
#include <cstdint>
#include <cmath>

// Problem constants (fixed by the dataset)
#define T_TOK 1024
#define H_DIM 2048
#define I_DIM 768
#define E_NUM 8
#define K_TOP 2
#define NROWS (T_TOK * K_TOP)      // 2048 permuted rows

#define BM1 64
#define MAX_TILES 40               // sum_e ceil(cnt_e/64) <= 39

// ---------------- scratch (no allocations allowed) ----------------
__device__ int   g_row_src[NROWS];
__device__ int   g_pos[NROWS];
__device__ int   g_tile_expert[MAX_TILES];   // BM=64 tiling (gemm1)
__device__ int   g_tile_row[MAX_TILES];
__device__ int   g_tile_end[MAX_TILES];
__device__ int   g_num_tiles;
__device__ int   g_tile2_expert[MAX_TILES];  // BM=128 tiling (gemm2)
__device__ int   g_tile2_row[MAX_TILES];
__device__ int   g_tile2_end[MAX_TILES];
__device__ int   g_num_tiles2;
__device__ float g_xc[T_TOK * H_DIM];     // tf32-rounded hidden_states
__device__ float g_act[NROWS * I_DIM];    // tf32-rounded swiglu output
__device__ float g_fc2[NROWS * H_DIM];

// ---------------- PTX helpers (all sm_80-level, no 'a' features) ----------------
__device__ __forceinline__ uint32_t s2u(const void* p) {
    uint32_t a;
    asm("{ .reg .u64 t; cvta.to.shared.u64 t, %1; cvt.u32.u64 %0, t; }" : "=r"(a) : "l"(p));
    return a;
}
__device__ __forceinline__ void cp16(uint32_t dst, const void* src, uint32_t sz) {
    asm volatile("cp.async.cg.shared.global [%0], [%1], 16, %2;" :: "r"(dst), "l"(src), "r"(sz));
}
__device__ __forceinline__ void cp_commit() { asm volatile("cp.async.commit_group;" ::: "memory"); }
template<int N> __device__ __forceinline__ void cp_wait() {
    asm volatile("cp.async.wait_group %0;" :: "n"(N) : "memory");
}
__device__ __forceinline__ void ldsm4(uint32_t r[4], uint32_t addr) {
    asm volatile("ldmatrix.sync.aligned.m8n8.x4.shared.b16 {%0,%1,%2,%3}, [%4];"
        : "=r"(r[0]), "=r"(r[1]), "=r"(r[2]), "=r"(r[3]) : "r"(addr));
}
__device__ __forceinline__ uint32_t f2tf_f(float x) {
    uint32_t r;
    asm("cvt.rna.tf32.f32 %0, %1;" : "=r"(r) : "f"(x));
    return r;
}
__device__ __forceinline__ float tfr(float x) {
    return __uint_as_float(f2tf_f(x));
}
__device__ __forceinline__ void mma8(float* c, const uint32_t* a, uint32_t b0, uint32_t b1) {
    asm volatile(
        "mma.sync.aligned.m16n8k8.row.col.f32.tf32.tf32.f32 "
        "{%0,%1,%2,%3}, {%4,%5,%6,%7}, {%8,%9}, {%0,%1,%2,%3};"
        : "+f"(c[0]), "+f"(c[1]), "+f"(c[2]), "+f"(c[3])
        : "r"(a[0]), "r"(a[1]), "r"(a[2]), "r"(a[3]), "r"(b0), "r"(b1));
}

// ---- gemm1 SMEM: 3 stages of {A 8KB (64x32f swizzled), B 17408B (32 x 136 f)}
#define G1_BPAD 136
#define G1_STAGE 25600
#define G1_OFF_A(b) ((b) * G1_STAGE)
#define G1_OFF_B(b) (G1_OFF_A(b) + 8192)
#define G1_SMEM 76800               // 3*(8192+17408); +1KB reserve x3 = 228KB exactly
// ---- gemm2 SMEM: 3 stages of {A 16KB (128x32f swizzled), B 17408B}
#define G2_BPAD 136
#define G2_STAGE 33792
#define G2_OFF_A(b) ((b) * G2_STAGE)
#define G2_OFF_B(b) (G2_OFF_A(b) + 16384)
#define G2_SMEM 101376

// ---------------- setup: counting sort + BOTH tilings ----------------
__global__ void setup_kernel(const int* __restrict__ sel) {
    __shared__ int cnt[E_NUM];
    __shared__ int run[E_NUM];
    int tid = threadIdx.x;
    if (tid < E_NUM) cnt[tid] = 0;
    __syncthreads();
    for (int i = tid; i < NROWS; i += blockDim.x)
        atomicAdd(&cnt[sel[i]], 1);
    __syncthreads();
    if (tid == 0) {
        int s = 0, nt = 0, nt2 = 0;
        for (int e = 0; e < E_NUM; e++) {
            run[e] = s;
            int c = cnt[e];
            for (int r = 0; r < c; r += BM1) {        // BM=64 tiles for gemm1
                g_tile_expert[nt] = e;
                g_tile_row[nt]    = s + r;
                g_tile_end[nt]    = s + c;
                nt++;
            }
            for (int r = 0; r < c; r += 128) {        // BM=128 tiles for gemm2
                g_tile2_expert[nt2] = e;
                g_tile2_row[nt2]    = s + r;
                g_tile2_end[nt2]    = s + c;
                nt2++;
            }
            s += c;
        }
        g_num_tiles = nt;
        g_num_tiles2 = nt2;
    }
    __syncthreads();
    for (int i = tid; i < NROWS; i += blockDim.x) {
        int e = sel[i];
        int p = atomicAdd(&run[e], 1);
        g_row_src[p] = i;
        g_pos[i] = p;
    }
}

// ---------------- cvtx: g_xc = tf32(x) ----------------
__global__ void __launch_bounds__(256)
cvtx_kernel(const float* __restrict__ x) {
    int i = blockIdx.x * blockDim.x + threadIdx.x;
    if (i >= T_TOK * (H_DIM / 4)) return;
    float4 v = reinterpret_cast<const float4*>(x)[i];
    v.x = tfr(v.x); v.y = tfr(v.y); v.z = tfr(v.z); v.w = tfr(v.w);
    reinterpret_cast<float4*>(g_xc)[i] = v;
}

// ---------------- GEMM1: act = swiglu( Xc_gather @ W1[e] ) ----------------
// Block: 64 rows x (gate 64 + up 64). Warps 2x4, warp tile 32x32. ks staggered by warpM.
__global__ void __launch_bounds__(256, 3)
gemm1_kernel(const float* __restrict__ w1) {
    extern __shared__ char smem[];
    uint32_t sb = s2u(smem);
    int mt = blockIdx.x;
    if (mt >= g_num_tiles) return;
    int e = g_tile_expert[mt], row0 = g_tile_row[mt], rend = g_tile_end[mt];
    int col0g = blockIdx.y * 64;

    int tid = threadIdx.x, lane = tid & 31, wid = tid >> 5;
    int warpM = wid >> 2, warpN = wid & 3;
    int gid = lane >> 2, tig = lane & 3;

    const float* W = w1 + (size_t)e * H_DIM * (2 * I_DIM);
    int am = tid >> 2;
    int ac0 = (tid & 3) * 2;
    int akey = am & 7;
    int arow = row0 + am;
    int tokm = (arow < rend) ? (g_row_src[arow] / K_TOP) : -1;
    const float* asrc = g_xc + (size_t)(tokm < 0 ? 0 : tokm) * H_DIM;
    uint32_t asz = (tokm < 0) ? 0u : 16u;

    auto load_chunk = [&](int ci, int buf) {
        int k0 = ci * 32;
        uint32_t Ab = sb + G1_OFF_A(buf);
        cp16(Ab + am * 128 + ((ac0 ^ akey) << 4),       asrc + k0 + ac0 * 4, asz);
        cp16(Ab + am * 128 + (((ac0 + 1) ^ akey) << 4), asrc + k0 + ac0 * 4 + 4, asz);
        uint32_t Bb = sb + G1_OFF_B(buf);
        #pragma unroll
        for (int it = 0; it < 4; it++) {
            int q = tid + it * 256;
            int k = q >> 5, c16 = q & 31, n = c16 * 4;
            const float* src = (n < 64)
                ? W + (size_t)(k0 + k) * (2 * I_DIM) + col0g + n
                : W + (size_t)(k0 + k) * (2 * I_DIM) + I_DIM + col0g + (n - 64);
            cp16(Bb + k * (G1_BPAD * 4) + n * 4, src, 16);
        }
        cp_commit();
    };

    int mlane = lane & 15, extra = lane >> 4, key = lane & 7;
    int boff = tig * G1_BPAD + warpN * 32 + gid;
    int ph = 2 * warpM;              // phase stagger across SMSP-coresident warps

    float acc[2][4][4] = {};
    const int NC = H_DIM / 32;   // 64
    load_chunk(0, 0);
    load_chunk(1, 1);
    int bc = 0;
    for (int i = 0; i < NC; i++) {
        cp_wait<1>();
        __syncthreads();
        int bn = bc + 2; if (bn >= 3) bn -= 3;
        if (i + 2 < NC) load_chunk(i + 2, bn);
        else            cp_commit();

        uint32_t Ab = sb + G1_OFF_A(bc);
        const float* Bsp = (const float*)(smem + G1_OFF_B(bc));
        #pragma unroll
        for (int ks = 0; ks < 4; ks++) {
            int kse = (ks + ph) & 3;
            uint32_t a[2][4];
            #pragma unroll
            for (int mi = 0; mi < 2; mi++) {
                uint32_t addr = Ab + (uint32_t)((warpM * 32 + mi * 16 + mlane) * 128
                              + ((((kse << 1) | extra) ^ key) << 4));
                ldsm4(a[mi], addr);
            }
            #pragma unroll
            for (int j = 0; j < 4; j++) {
                uint32_t b0 = f2tf_f(Bsp[boff + kse * (8 * G1_BPAD) + j * 8]);
                uint32_t b1 = f2tf_f(Bsp[boff + kse * (8 * G1_BPAD) + j * 8 + 4 * G1_BPAD]);
                mma8(acc[0][j], a[0], b0, b1);
                mma8(acc[1][j], a[1], b0, b1);
            }
        }
        bc = (bc + 1 == 3) ? 0 : bc + 1;
    }

    // epilogue: frags -> smem (stride 132), then swiglu (tf32-rounded) -> g_act
    __syncthreads();
    float* Es = (float*)smem;
    #pragma unroll
    for (int mi = 0; mi < 2; mi++)
        #pragma unroll
        for (int j = 0; j < 4; j++) {
            int row = warpM * 32 + mi * 16 + gid;
            int col = warpN * 32 + j * 8 + 2 * tig;
            *(float2*)&Es[row * 132 + col]       = make_float2(acc[mi][j][0], acc[mi][j][1]);
            *(float2*)&Es[(row + 8) * 132 + col] = make_float2(acc[mi][j][2], acc[mi][j][3]);
        }
    __syncthreads();

    int rr = tid >> 2;                 // 0..63
    int r  = row0 + rr;
    int cb = (tid & 3) * 16;           // 0,16,32,48
    if (r < rend) {
        float* dst = g_act + (size_t)r * I_DIM + col0g + cb;
        #pragma unroll
        for (int jj = 0; jj < 16; jj += 4) {
            float4 gv = *(float4*)&Es[rr * 132 + cb + jj];
            float4 uv = *(float4*)&Es[rr * 132 + 64 + cb + jj];
            float4 o;
            o.x = tfr(gv.x * (1.0f / (1.0f + __expf(-gv.x))) * uv.x);
            o.y = tfr(gv.y * (1.0f / (1.0f + __expf(-gv.y))) * uv.y);
            o.z = tfr(gv.z * (1.0f / (1.0f + __expf(-gv.z))) * uv.z);
            o.w = tfr(gv.w * (1.0f / (1.0f + __expf(-gv.w))) * uv.w);
            *(float4*)(dst + jj) = o;
        }
    }
}

// ---------------- GEMM2: fc2 = act @ W2[e] ----------------
// Block: 128 rows x 128 cols. Warps 2x4, warp tile 64x32. Pipelined frags + ks stagger.
__global__ void __launch_bounds__(256, 2)
gemm2_kernel(const float* __restrict__ w2) {
    extern __shared__ char smem[];
    uint32_t sb = s2u(smem);
    int mt = blockIdx.x;
    if (mt >= g_num_tiles2) return;
    int e = g_tile2_expert[mt], row0 = g_tile2_row[mt], rend = g_tile2_end[mt];
    int col0 = blockIdx.y * 128;

    int tid = threadIdx.x, lane = tid & 31, wid = tid >> 5;
    int warpM = wid >> 2, warpN = wid & 3;
    int gid = lane >> 2, tig = lane & 3;

    const float* W = w2 + (size_t)e * I_DIM * H_DIM;
    int am = tid >> 1;
    int rrow = row0 + am; if (rrow >= NROWS) rrow = NROWS - 1;   // clamp; masked later
    const float* asrc = g_act + (size_t)rrow * I_DIM;
    int ac0 = (tid & 1) * 4;
    int akey = am & 7;

    auto load_chunk = [&](int ci, int buf) {
        int k0 = ci * 32;
        uint32_t Ab = sb + G2_OFF_A(buf);
        #pragma unroll
        for (int c = 0; c < 4; c++) {
            int cc = ac0 + c;
            cp16(Ab + am * 128 + ((cc ^ akey) << 4), asrc + k0 + cc * 4, 16);
        }
        uint32_t Bb = sb + G2_OFF_B(buf);
        #pragma unroll
        for (int it = 0; it < 4; it++) {
            int q = tid + it * 256;
            int k = q >> 5, c16 = q & 31, n = c16 * 4;
            cp16(Bb + k * (G2_BPAD * 4) + n * 4, W + (size_t)(k0 + k) * H_DIM + col0 + n, 16);
        }
        cp_commit();
    };

    int mlane = lane & 15, extra = lane >> 4, key = lane & 7;
    int boff = tig * G2_BPAD + warpN * 32 + gid;
    uint32_t arow = (uint32_t)((warpM * 64 + mlane) * 128);
    int ph = 2 * warpM;

    float acc[4][4][4] = {};
    uint32_t af[2][4][4];
    uint32_t bf[2][8];
    const int NC = I_DIM / 32;   // 24
    load_chunk(0, 0);
    load_chunk(1, 1);
    int bc = 0;
    for (int i = 0; i < NC; i++) {
        cp_wait<1>();
        __syncthreads();
        int bn = bc + 2; if (bn >= 3) bn -= 3;
        if (i + 2 < NC) load_chunk(i + 2, bn);
        else            cp_commit();

        uint32_t Ab = sb + G2_OFF_A(bc) + arow;
        const float* Bsp = (const float*)(smem + G2_OFF_B(bc));
        int kse0 = ph;               // first ks for this warp
        #pragma unroll
        for (int mi = 0; mi < 4; mi++)
            ldsm4(af[0][mi], Ab + mi * (16 * 128) + ((((kse0 << 1) | extra) ^ key) << 4));
        #pragma unroll
        for (int j = 0; j < 4; j++) {
            bf[0][2 * j]     = f2tf_f(Bsp[boff + kse0 * (8 * G2_BPAD) + j * 8]);
            bf[0][2 * j + 1] = f2tf_f(Bsp[boff + kse0 * (8 * G2_BPAD) + j * 8 + 4 * G2_BPAD]);
        }
        #pragma unroll
        for (int ks = 0; ks < 4; ks++) {
            int cur = ks & 1, nxt = cur ^ 1;
            if (ks < 3) {   // prefetch next ks fragments BEFORE the mma block
                int ksn = (ks + 1 + ph) & 3;
                #pragma unroll
                for (int mi = 0; mi < 4; mi++)
                    ldsm4(af[nxt][mi], Ab + mi * (16 * 128)
                          + ((((ksn << 1) | extra) ^ key) << 4));
                #pragma unroll
                for (int j = 0; j < 4; j++) {
                    bf[nxt][2 * j]     = f2tf_f(Bsp[boff + ksn * (8 * G2_BPAD) + j * 8]);
                    bf[nxt][2 * j + 1] = f2tf_f(Bsp[boff + ksn * (8 * G2_BPAD) + j * 8 + 4 * G2_BPAD]);
                }
            }
            #pragma unroll
            for (int j = 0; j < 4; j++)
                #pragma unroll
                for (int mi = 0; mi < 4; mi++)
                    mma8(acc[mi][j], af[cur][mi], bf[cur][2 * j], bf[cur][2 * j + 1]);
        }
        bc = (bc + 1 == 3) ? 0 : bc + 1;
    }

    // epilogue: direct to g_fc2
    #pragma unroll
    for (int mi = 0; mi < 4; mi++) {
        int row = row0 + warpM * 64 + mi * 16 + gid;
        #pragma unroll
        for (int j = 0; j < 4; j++) {
            int col = col0 + warpN * 32 + j * 8 + 2 * tig;
            if (row < rend)
                *(float2*)&g_fc2[(size_t)row * H_DIM + col] =
                    make_float2(acc[mi][j][0], acc[mi][j][1]);
            if (row + 8 < rend)
                *(float2*)&g_fc2[(size_t)(row + 8) * H_DIM + col] =
                    make_float2(acc[mi][j][2], acc[mi][j][3]);
        }
    }
}

// ---------------- combine ----------------
__global__ void __launch_bounds__(256)
combine_kernel(const float* __restrict__ rw, float* __restrict__ out) {
    int i = blockIdx.x * blockDim.x + threadIdx.x;
    if (i >= T_TOK * (H_DIM / 4)) return;
    int t  = i >> 9;
    int h4 = i & 511;
    int p0 = g_pos[2 * t];
    int p1 = g_pos[2 * t + 1];
    float w0 = rw[2 * t];
    float w1 = rw[2 * t + 1];
    float4 v0 = *reinterpret_cast<const float4*>(&g_fc2[(size_t)p0 * H_DIM + h4 * 4]);
    float4 v1 = *reinterpret_cast<const float4*>(&g_fc2[(size_t)p1 * H_DIM + h4 * 4]);
    float4 o;
    o.x = w0 * v0.x + w1 * v1.x;
    o.y = w0 * v0.y + w1 * v1.y;
    o.z = w0 * v0.z + w1 * v1.z;
    o.w = w0 * v0.w + w1 * v1.w;
    reinterpret_cast<float4*>(out)[i] = o;
}

// ---------------- launch ----------------
extern "C" void kernel_launch(void* const* d_in, const int* in_sizes, int n_in,
                              void* d_out, int out_size) {
    const float* x   = (const float*)d_in[0];   // hidden_states [T, H]
    const float* rw  = (const float*)d_in[1];   // routing_weights [T, K]
    const float* w1  = (const float*)d_in[2];   // gate_up_proj [E, H, 2I]
    const float* w2  = (const float*)d_in[3];   // down_proj   [E, I, H]
    const int*   sel = (const int*)d_in[4];     // selected_experts [T, K]
    float* out = (float*)d_out;                 // [T, H] fp32

    cudaFuncSetAttribute(gemm1_kernel, cudaFuncAttributeMaxDynamicSharedMemorySize, G1_SMEM);
    cudaFuncSetAttribute(gemm2_kernel, cudaFuncAttributeMaxDynamicSharedMemorySize, G2_SMEM);

    setup_kernel<<<1, 256>>>(sel);
    cvtx_kernel<<<(T_TOK * H_DIM / 4 + 255) / 256, 256>>>(x);
    gemm1_kernel<<<dim3(MAX_TILES, I_DIM / 64), 256, G1_SMEM>>>(w1);
    gemm2_kernel<<<dim3(24, H_DIM / 128), 256, G2_SMEM>>>(w2);
    combine_kernel<<<(T_TOK * H_DIM / 4 + 255) / 256, 256>>>(rw, out);
}